// round 4
// baseline (speedup 1.0000x reference)
#include <cuda_runtime.h>
#include <cuda_bf16.h>

// Problem constants (from reference: N=100000, F=128, Fo=64, E=1600000)
#define NMAX 100000
#define FDIM 128
#define FO   64

// Scratch (static device globals — no allocation allowed). 16B alignment is
// REQUIRED: float4 ld/st and red.global.add.v4.f32 trap on misaligned addr.
__device__ __align__(16) float g_deg[NMAX];        // degree incl. self loop
__device__ __align__(16) float g_hs [NMAX * FO];   // h[i] * dinv[i]
__device__ __align__(16) float g_tmp[NMAX * FO];   // aggregate (init = hs -> self loop)

// ---------------------------------------------------------------------------
// K0: deg init (self loop contributes 1)
__global__ void k_deg_init(int N) {
    int i = blockIdx.x * blockDim.x + threadIdx.x;
    if (i < N) g_deg[i] = 1.0f;
}

// K1: deg accumulate over dst
__global__ void k_deg_acc(const int* __restrict__ ei, int E) {
    int e = blockIdx.x * blockDim.x + threadIdx.x;
    if (e < E) {
        int dst = ei[E + e];
        atomicAdd(&g_deg[dst], 1.0f);
    }
}

// ---------------------------------------------------------------------------
// K2: hs = (x @ W^T) * dinv ; tmp = hs (self-loop init)
// Block: 128 threads, 16 rows per block. W kept k-major in shared.
// WPAD must be a multiple of 4 so float4 row loads stay 16B-aligned.
#define ROWS_PER_BLK 16
#define WPAD 68

__global__ __launch_bounds__(128) void k_gemm(const float* __restrict__ x,
                                              const float* __restrict__ W,
                                              int N) {
    __shared__ float W_sh[FDIM * WPAD];        // W_sh[k*WPAD + c] = W[c*128 + k]
    __shared__ float x_sh[ROWS_PER_BLK * FDIM];

    int tid = threadIdx.x;

    // load W transposed (k-major) — 8192 elements
    #pragma unroll
    for (int i = tid; i < FO * FDIM; i += 128) {
        int c = i >> 7;        // 0..63
        int k = i & 127;       // 0..127
        W_sh[k * WPAD + c] = W[i];
    }

    int row0 = blockIdx.x * ROWS_PER_BLK;
    // load x rows (coalesced)
    #pragma unroll
    for (int i = tid; i < ROWS_PER_BLK * FDIM; i += 128) {
        int r = i >> 7;
        int k = i & 127;
        int gr = row0 + r;
        x_sh[i] = (gr < N) ? x[(long)gr * FDIM + k] : 0.0f;
    }
    __syncthreads();

    int r  = tid >> 3;          // 0..15 (row within block)
    int c0 = (tid & 7) << 3;    // 0,8,...,56 (8 output cols per thread)

    float acc[8];
    #pragma unroll
    for (int j = 0; j < 8; j++) acc[j] = 0.0f;

    const float* xr = &x_sh[r * FDIM];
    #pragma unroll 8
    for (int k = 0; k < FDIM; k += 4) {
        float4 xv = *(const float4*)(xr + k);
        #pragma unroll
        for (int kk = 0; kk < 4; kk++) {
            float xs = (kk == 0) ? xv.x : (kk == 1) ? xv.y : (kk == 2) ? xv.z : xv.w;
            float4 w0 = *(const float4*)(&W_sh[(k + kk) * WPAD + c0]);
            float4 w1 = *(const float4*)(&W_sh[(k + kk) * WPAD + c0 + 4]);
            acc[0] = fmaf(xs, w0.x, acc[0]);
            acc[1] = fmaf(xs, w0.y, acc[1]);
            acc[2] = fmaf(xs, w0.z, acc[2]);
            acc[3] = fmaf(xs, w0.w, acc[3]);
            acc[4] = fmaf(xs, w1.x, acc[4]);
            acc[5] = fmaf(xs, w1.y, acc[5]);
            acc[6] = fmaf(xs, w1.z, acc[6]);
            acc[7] = fmaf(xs, w1.w, acc[7]);
        }
    }

    int gr = row0 + r;
    if (gr < N) {
        float dinv = rsqrtf(g_deg[gr]);
        float4 v0 = make_float4(acc[0] * dinv, acc[1] * dinv, acc[2] * dinv, acc[3] * dinv);
        float4 v1 = make_float4(acc[4] * dinv, acc[5] * dinv, acc[6] * dinv, acc[7] * dinv);
        long base = (long)gr * FO + c0;
        *(float4*)&g_hs [base]     = v0;
        *(float4*)&g_hs [base + 4] = v1;
        *(float4*)&g_tmp[base]     = v0;   // self-loop contribution
        *(float4*)&g_tmp[base + 4] = v1;
    }
}

// ---------------------------------------------------------------------------
// K3: scatter-add: tmp[dst] += hs[src]   (16 threads per edge, float4 RED)
__global__ void k_scatter(const int* __restrict__ ei, int E) {
    long t = (long)blockIdx.x * blockDim.x + threadIdx.x;
    int e = (int)(t >> 4);
    if (e >= E) return;
    int j   = ((int)t & 15) << 2;         // 0,4,...,60
    int src = ei[e];
    int dst = ei[E + e];
    float4 v = *(const float4*)&g_hs[(long)src * FO + j];
    float* p = &g_tmp[(long)dst * FO + j];
    asm volatile("red.global.add.v4.f32 [%0], {%1, %2, %3, %4};"
                 :: "l"(p), "f"(v.x), "f"(v.y), "f"(v.z), "f"(v.w)
                 : "memory");
}

// ---------------------------------------------------------------------------
// K4: out = sigmoid( relu(dinv*tmp + b_conv) . W_lin + b_lin )  — warp per node
__global__ void k_final(const float* __restrict__ Wl,
                        const float* __restrict__ bl,
                        const float* __restrict__ bconv,
                        float* __restrict__ out, int N) {
    int warp = (int)((blockIdx.x * blockDim.x + threadIdx.x) >> 5);
    int lane = threadIdx.x & 31;
    if (warp >= N) return;

    float dinv = rsqrtf(g_deg[warp]);
    float2 tv = *(const float2*)&g_tmp[(long)warp * FO + lane * 2];
    float2 wv = *(const float2*)&Wl[lane * 2];
    float2 bc = *(const float2*)&bconv[lane * 2];

    float v0 = fmaxf(fmaf(tv.x, dinv, bc.x), 0.0f);
    float v1 = fmaxf(fmaf(tv.y, dinv, bc.y), 0.0f);
    float s  = v0 * wv.x + v1 * wv.y;

    #pragma unroll
    for (int o = 16; o; o >>= 1) s += __shfl_xor_sync(0xFFFFFFFFu, s, o);

    if (lane == 0) {
        float z = s + bl[0];
        out[warp] = 1.0f / (1.0f + expf(-z));
    }
}

// ---------------------------------------------------------------------------
extern "C" void kernel_launch(void* const* d_in, const int* in_sizes, int n_in,
                              void* d_out, int out_size) {
    const float* x     = (const float*)d_in[0];
    const int*   ei    = (const int*)  d_in[1];
    const float* Wc    = (const float*)d_in[2];
    const float* bc    = (const float*)d_in[3];
    const float* Wl    = (const float*)d_in[4];
    const float* bl    = (const float*)d_in[5];
    float*       out   = (float*)d_out;

    int N = in_sizes[0] / FDIM;
    int E = in_sizes[1] / 2;
    if (N > NMAX) N = NMAX;

    k_deg_init<<<(N + 255) / 256, 256>>>(N);
    k_deg_acc <<<(E + 255) / 256, 256>>>(ei, E);
    k_gemm    <<<(N + ROWS_PER_BLK - 1) / ROWS_PER_BLK, 128>>>(x, Wc, N);
    {
        long threads = (long)E * 16;
        int blocks = (int)((threads + 255) / 256);
        k_scatter<<<blocks, 256>>>(ei, E);
    }
    k_final<<<(N + 7) / 8, 256>>>(Wl, bl, bc, out, N);
}

// round 5
// speedup vs baseline: 1.2799x; 1.2799x over previous
#include <cuda_runtime.h>
#include <cuda_bf16.h>

// Problem constants (from reference: N=100000, F=128, Fo=64, E=1600000)
#define NMAX 100000
#define FDIM 128
#define FO   64

// Scratch (static device globals). 16B alignment REQUIRED for float4 / red.v4.
__device__ __align__(16) float g_deg[NMAX];
__device__ __align__(16) float g_hs [NMAX * FO];   // h[i] * dinv[i]
__device__ __align__(16) float g_tmp[NMAX * FO];   // aggregate (init = hs -> self loop)

// ---- packed f32x2 helpers (sm_103a) ---------------------------------------
__device__ __forceinline__ unsigned long long pk2(float s) {
    unsigned long long r;
    asm("mov.b64 %0, {%1, %1};" : "=l"(r) : "f"(s));
    return r;
}
__device__ __forceinline__ void fma2(unsigned long long& d,
                                     unsigned long long a,
                                     unsigned long long b) {
    asm("fma.rn.f32x2 %0, %1, %2, %0;" : "+l"(d) : "l"(a), "l"(b));
}
__device__ __forceinline__ float2 unpk2(unsigned long long v) {
    float2 f;
    asm("mov.b64 {%0, %1}, %2;" : "=f"(f.x), "=f"(f.y) : "l"(v));
    return f;
}

// ---------------------------------------------------------------------------
// K0: deg init (self loop contributes 1)
__global__ void k_deg_init(int N) {
    int i = blockIdx.x * blockDim.x + threadIdx.x;
    if (i < N) g_deg[i] = 1.0f;
}

// K1: deg accumulate over dst (4 edges/thread, int4 load)
__global__ void k_deg_acc(const int* __restrict__ ei, int E) {
    int t = blockIdx.x * blockDim.x + threadIdx.x;
    int e0 = t * 4;
    if (e0 + 3 < E) {
        int4 d = *(const int4*)(ei + E + e0);
        atomicAdd(&g_deg[d.x], 1.0f);
        atomicAdd(&g_deg[d.y], 1.0f);
        atomicAdd(&g_deg[d.z], 1.0f);
        atomicAdd(&g_deg[d.w], 1.0f);
    } else {
        for (int e = e0; e < E; e++) atomicAdd(&g_deg[ei[E + e]], 1.0f);
    }
}

// ---------------------------------------------------------------------------
// K2: hs = (x @ W^T) * dinv ; tmp = hs (self-loop init)
// 128 threads, 32 rows/block. Each thread: 2 rows (r, r+16) x 8 cols, packed
// f32x2 accumulators. Smem: W k-major 128x64 (32KB) + x k-major swizzled
// 128x32 (16KB) = 48KB exactly.
#define ROWS_PER_BLK 32

__global__ __launch_bounds__(128) void k_gemm(const float* __restrict__ x,
                                              const float* __restrict__ W,
                                              int N) {
    __shared__ float W_sh[FDIM * FO];           // W_sh[k*64 + c] = W[c*128 + k]
    __shared__ float x_sh[FDIM * ROWS_PER_BLK]; // x_sh[k*32 + ((r+k)&31)] = x[row0+r][k]

    int tid = threadIdx.x;
    int row0 = blockIdx.x * ROWS_PER_BLK;

    // load W transposed (k-major)
    #pragma unroll
    for (int i = tid; i < FO * FDIM; i += 128) {
        int c = i >> 7;        // 0..63
        int k = i & 127;       // 0..127
        W_sh[k * FO + c] = W[i];
    }

    // load x rows, coalesced read -> swizzled k-major store (conflict-free)
    #pragma unroll
    for (int i = tid; i < ROWS_PER_BLK * FDIM; i += 128) {
        int r = i >> 7;        // 0..31
        int k = i & 127;
        int gr = row0 + r;
        float v = (gr < N) ? x[(long)gr * FDIM + k] : 0.0f;
        x_sh[k * ROWS_PER_BLK + ((r + k) & 31)] = v;
    }
    __syncthreads();

    int r  = tid >> 3;          // 0..15: this thread does rows r and r+16
    int c0 = (tid & 7) << 3;    // 0,8,...,56

    unsigned long long accA[4], accB[4];
    #pragma unroll
    for (int j = 0; j < 4; j++) { accA[j] = 0ull; accB[j] = 0ull; }

    #pragma unroll 4
    for (int k = 0; k < FDIM; k++) {
        float xa = x_sh[k * ROWS_PER_BLK + ((r + k) & 31)];
        float xb = x_sh[k * ROWS_PER_BLK + ((r + 16 + k) & 31)];
        unsigned long long pa = pk2(xa);
        unsigned long long pb = pk2(xb);
        const ulonglong2* wrow = (const ulonglong2*)&W_sh[k * FO + c0];
        ulonglong2 w01 = wrow[0];   // cols c0..c0+3 as two f32x2
        ulonglong2 w23 = wrow[1];   // cols c0+4..c0+7
        fma2(accA[0], pa, w01.x);  fma2(accA[1], pa, w01.y);
        fma2(accA[2], pa, w23.x);  fma2(accA[3], pa, w23.y);
        fma2(accB[0], pb, w01.x);  fma2(accB[1], pb, w01.y);
        fma2(accB[2], pb, w23.x);  fma2(accB[3], pb, w23.y);
    }

    #pragma unroll
    for (int half = 0; half < 2; half++) {
        int gr = row0 + r + half * 16;
        if (gr >= N) continue;
        unsigned long long* acc = half ? accB : accA;
        float dinv = rsqrtf(g_deg[gr]);
        float2 p0 = unpk2(acc[0]), p1 = unpk2(acc[1]);
        float2 p2 = unpk2(acc[2]), p3 = unpk2(acc[3]);
        float4 v0 = make_float4(p0.x * dinv, p0.y * dinv, p1.x * dinv, p1.y * dinv);
        float4 v1 = make_float4(p2.x * dinv, p2.y * dinv, p3.x * dinv, p3.y * dinv);
        long base = (long)gr * FO + c0;
        *(float4*)&g_hs [base]     = v0;
        *(float4*)&g_hs [base + 4] = v1;
        *(float4*)&g_tmp[base]     = v0;   // self-loop contribution
        *(float4*)&g_tmp[base + 4] = v1;
    }
}

// ---------------------------------------------------------------------------
// K3: scatter-add: tmp[dst] += hs[src]   (16 threads per edge, float4 RED)
__global__ void k_scatter(const int* __restrict__ ei, int E) {
    long t = (long)blockIdx.x * blockDim.x + threadIdx.x;
    int e = (int)(t >> 4);
    if (e >= E) return;
    int j   = ((int)t & 15) << 2;         // 0,4,...,60
    int src = ei[e];
    int dst = ei[E + e];
    float4 v = __ldg((const float4*)&g_hs[(long)src * FO + j]);
    float* p = &g_tmp[(long)dst * FO + j];
    asm volatile("red.global.add.v4.f32 [%0], {%1, %2, %3, %4};"
                 :: "l"(p), "f"(v.x), "f"(v.y), "f"(v.z), "f"(v.w)
                 : "memory");
}

// ---------------------------------------------------------------------------
// K4: out = sigmoid( relu(dinv*tmp + b_conv) . W_lin + b_lin )  — warp per node
__global__ void k_final(const float* __restrict__ Wl,
                        const float* __restrict__ bl,
                        const float* __restrict__ bconv,
                        float* __restrict__ out, int N) {
    int warp = (int)((blockIdx.x * blockDim.x + threadIdx.x) >> 5);
    int lane = threadIdx.x & 31;
    if (warp >= N) return;

    float dinv = rsqrtf(g_deg[warp]);
    float2 tv = *(const float2*)&g_tmp[(long)warp * FO + lane * 2];
    float2 wv = *(const float2*)&Wl[lane * 2];
    float2 bc = *(const float2*)&bconv[lane * 2];

    float v0 = fmaxf(fmaf(tv.x, dinv, bc.x), 0.0f);
    float v1 = fmaxf(fmaf(tv.y, dinv, bc.y), 0.0f);
    float s  = v0 * wv.x + v1 * wv.y;

    #pragma unroll
    for (int o = 16; o; o >>= 1) s += __shfl_xor_sync(0xFFFFFFFFu, s, o);

    if (lane == 0) {
        float z = s + bl[0];
        out[warp] = 1.0f / (1.0f + expf(-z));
    }
}

// ---------------------------------------------------------------------------
extern "C" void kernel_launch(void* const* d_in, const int* in_sizes, int n_in,
                              void* d_out, int out_size) {
    const float* x     = (const float*)d_in[0];
    const int*   ei    = (const int*)  d_in[1];
    const float* Wc    = (const float*)d_in[2];
    const float* bc    = (const float*)d_in[3];
    const float* Wl    = (const float*)d_in[4];
    const float* bl    = (const float*)d_in[5];
    float*       out   = (float*)d_out;

    int N = in_sizes[0] / FDIM;
    int E = in_sizes[1] / 2;
    if (N > NMAX) N = NMAX;

    k_deg_init<<<(N + 255) / 256, 256>>>(N);
    k_deg_acc <<<((E + 3) / 4 + 255) / 256, 256>>>(ei, E);
    k_gemm    <<<(N + ROWS_PER_BLK - 1) / ROWS_PER_BLK, 128>>>(x, Wc, N);
    {
        long threads = (long)E * 16;
        int blocks = (int)((threads + 255) / 256);
        k_scatter<<<blocks, 256>>>(ei, E);
    }
    k_final<<<(N + 7) / 8, 256>>>(Wl, bl, bc, out, N);
}

// round 6
// speedup vs baseline: 1.4005x; 1.0942x over previous
#include <cuda_runtime.h>
#include <cuda_bf16.h>

// Problem constants (from reference: N=100000, F=128, Fo=64, E=1600000)
#define NMAX 100000
#define FDIM 128
#define FO   64

// Scratch (static device globals). 16B alignment REQUIRED for float4 / red.v4.
__device__ __align__(16) float g_deg[NMAX];
__device__ __align__(16) float g_hs [NMAX * FO];   // h[i] * dinv[i]
__device__ __align__(16) float g_tmp[NMAX * FO];   // aggregate (init = hs -> self loop)

// ---- packed f32x2 helpers (sm_103a) ---------------------------------------
__device__ __forceinline__ unsigned long long pk2(float s) {
    unsigned long long r;
    asm("mov.b64 %0, {%1, %1};" : "=l"(r) : "f"(s));
    return r;
}
__device__ __forceinline__ void fma2(unsigned long long& d,
                                     unsigned long long a,
                                     unsigned long long b) {
    asm("fma.rn.f32x2 %0, %1, %2, %0;" : "+l"(d) : "l"(a), "l"(b));
}
__device__ __forceinline__ float2 unpk2(unsigned long long v) {
    float2 f;
    asm("mov.b64 {%0, %1}, %2;" : "=f"(f.x), "=f"(f.y) : "l"(v));
    return f;
}

// ---------------------------------------------------------------------------
// K0: deg init (self loop contributes 1)
__global__ void k_deg_init(int N) {
    int i = blockIdx.x * blockDim.x + threadIdx.x;
    if (i < N) g_deg[i] = 1.0f;
}

// K1: deg accumulate over dst (4 edges/thread, int4 load)
__global__ void k_deg_acc(const int* __restrict__ ei, int E) {
    int t = blockIdx.x * blockDim.x + threadIdx.x;
    int e0 = t * 4;
    if (e0 + 3 < E) {
        int4 d = *(const int4*)(ei + E + e0);
        atomicAdd(&g_deg[d.x], 1.0f);
        atomicAdd(&g_deg[d.y], 1.0f);
        atomicAdd(&g_deg[d.z], 1.0f);
        atomicAdd(&g_deg[d.w], 1.0f);
    } else {
        for (int e = e0; e < E; e++) atomicAdd(&g_deg[ei[E + e]], 1.0f);
    }
}

// ---------------------------------------------------------------------------
// K2: hs = (x @ W^T) * dinv ; tmp = hs (self-loop init)
// 128 threads, 32 rows/block, packed f32x2 accumulators. (unchanged from R5)
#define ROWS_PER_BLK 32

__global__ __launch_bounds__(128) void k_gemm(const float* __restrict__ x,
                                              const float* __restrict__ W,
                                              int N) {
    __shared__ float W_sh[FDIM * FO];           // W_sh[k*64 + c] = W[c*128 + k]
    __shared__ float x_sh[FDIM * ROWS_PER_BLK]; // x_sh[k*32 + ((r+k)&31)]

    int tid = threadIdx.x;
    int row0 = blockIdx.x * ROWS_PER_BLK;

    #pragma unroll
    for (int i = tid; i < FO * FDIM; i += 128) {
        int c = i >> 7;
        int k = i & 127;
        W_sh[k * FO + c] = W[i];
    }

    #pragma unroll
    for (int i = tid; i < ROWS_PER_BLK * FDIM; i += 128) {
        int r = i >> 7;
        int k = i & 127;
        int gr = row0 + r;
        float v = (gr < N) ? x[(long)gr * FDIM + k] : 0.0f;
        x_sh[k * ROWS_PER_BLK + ((r + k) & 31)] = v;
    }
    __syncthreads();

    int r  = tid >> 3;
    int c0 = (tid & 7) << 3;

    unsigned long long accA[4], accB[4];
    #pragma unroll
    for (int j = 0; j < 4; j++) { accA[j] = 0ull; accB[j] = 0ull; }

    #pragma unroll 4
    for (int k = 0; k < FDIM; k++) {
        float xa = x_sh[k * ROWS_PER_BLK + ((r + k) & 31)];
        float xb = x_sh[k * ROWS_PER_BLK + ((r + 16 + k) & 31)];
        unsigned long long pa = pk2(xa);
        unsigned long long pb = pk2(xb);
        const ulonglong2* wrow = (const ulonglong2*)&W_sh[k * FO + c0];
        ulonglong2 w01 = wrow[0];
        ulonglong2 w23 = wrow[1];
        fma2(accA[0], pa, w01.x);  fma2(accA[1], pa, w01.y);
        fma2(accA[2], pa, w23.x);  fma2(accA[3], pa, w23.y);
        fma2(accB[0], pb, w01.x);  fma2(accB[1], pb, w01.y);
        fma2(accB[2], pb, w23.x);  fma2(accB[3], pb, w23.y);
    }

    #pragma unroll
    for (int half = 0; half < 2; half++) {
        int gr = row0 + r + half * 16;
        if (gr >= N) continue;
        unsigned long long* acc = half ? accB : accA;
        float dinv = rsqrtf(g_deg[gr]);
        float2 p0 = unpk2(acc[0]), p1 = unpk2(acc[1]);
        float2 p2 = unpk2(acc[2]), p3 = unpk2(acc[3]);
        float4 v0 = make_float4(p0.x * dinv, p0.y * dinv, p1.x * dinv, p1.y * dinv);
        float4 v1 = make_float4(p2.x * dinv, p2.y * dinv, p3.x * dinv, p3.y * dinv);
        long base = (long)gr * FO + c0;
        *(float4*)&g_hs [base]     = v0;
        *(float4*)&g_hs [base + 4] = v1;
        *(float4*)&g_tmp[base]     = v0;
        *(float4*)&g_tmp[base + 4] = v1;
    }
}

// ---------------------------------------------------------------------------
// K3: scatter-add: tmp[dst] += hs[src]  — WARP PER EDGE, one line per instr.
// Each LDG.32 / RED.32 covers 32 lanes x 4B = exactly one 128B line, so every
// memory instruction is a single L1tex wavefront (1.0 cyc/wf cross-LDG rate)
// instead of packing 4 random lines into one LDG.128 (2.07 cyc/wf replays).
// A warp batches 32 edges: coalesced src/dst load, then shfl-broadcast loop.
__global__ __launch_bounds__(256) void k_scatter(const int* __restrict__ ei, int E) {
    int warp = (int)((blockIdx.x * blockDim.x + threadIdx.x) >> 5);
    int lane = threadIdx.x & 31;
    int e0 = warp << 5;                 // first edge of this warp's batch
    if (e0 >= E) return;
    int n = E - e0; if (n > 32) n = 32;

    int mysrc = 0, mydst = 0;
    if (lane < n) {
        mysrc = __ldg(ei + e0 + lane);
        mydst = __ldg(ei + E + e0 + lane);
    }

    #pragma unroll 4
    for (int i = 0; i < n; i++) {
        int src = __shfl_sync(0xFFFFFFFFu, mysrc, i);
        int dst = __shfl_sync(0xFFFFFFFFu, mydst, i);
        const float* hp = g_hs + (long)src * FO;
        float v0 = __ldg(hp + lane);         // line 0 of src row
        float v1 = __ldg(hp + 32 + lane);    // line 1 of src row
        float* tp = g_tmp + (long)dst * FO;
        asm volatile("red.global.add.f32 [%0], %1;"
                     :: "l"(tp + lane), "f"(v0) : "memory");
        asm volatile("red.global.add.f32 [%0], %1;"
                     :: "l"(tp + 32 + lane), "f"(v1) : "memory");
    }
}

// ---------------------------------------------------------------------------
// K4: out = sigmoid( relu(dinv*tmp + b_conv) . W_lin + b_lin )  — warp per node
__global__ void k_final(const float* __restrict__ Wl,
                        const float* __restrict__ bl,
                        const float* __restrict__ bconv,
                        float* __restrict__ out, int N) {
    int warp = (int)((blockIdx.x * blockDim.x + threadIdx.x) >> 5);
    int lane = threadIdx.x & 31;
    if (warp >= N) return;

    float dinv = rsqrtf(g_deg[warp]);
    float2 tv = *(const float2*)&g_tmp[(long)warp * FO + lane * 2];
    float2 wv = *(const float2*)&Wl[lane * 2];
    float2 bc = *(const float2*)&bconv[lane * 2];

    float v0 = fmaxf(fmaf(tv.x, dinv, bc.x), 0.0f);
    float v1 = fmaxf(fmaf(tv.y, dinv, bc.y), 0.0f);
    float s  = v0 * wv.x + v1 * wv.y;

    #pragma unroll
    for (int o = 16; o; o >>= 1) s += __shfl_xor_sync(0xFFFFFFFFu, s, o);

    if (lane == 0) {
        float z = s + bl[0];
        out[warp] = 1.0f / (1.0f + expf(-z));
    }
}

// ---------------------------------------------------------------------------
extern "C" void kernel_launch(void* const* d_in, const int* in_sizes, int n_in,
                              void* d_out, int out_size) {
    const float* x     = (const float*)d_in[0];
    const int*   ei    = (const int*)  d_in[1];
    const float* Wc    = (const float*)d_in[2];
    const float* bc    = (const float*)d_in[3];
    const float* Wl    = (const float*)d_in[4];
    const float* bl    = (const float*)d_in[5];
    float*       out   = (float*)d_out;

    int N = in_sizes[0] / FDIM;
    int E = in_sizes[1] / 2;
    if (N > NMAX) N = NMAX;

    k_deg_init<<<(N + 255) / 256, 256>>>(N);
    k_deg_acc <<<((E + 3) / 4 + 255) / 256, 256>>>(ei, E);
    k_gemm    <<<(N + ROWS_PER_BLK - 1) / ROWS_PER_BLK, 128>>>(x, Wc, N);
    {
        int nwarp  = (E + 31) / 32;              // one warp per 32-edge batch
        int blocks = (nwarp + 7) / 8;            // 8 warps (256 thr) per block
        k_scatter<<<blocks, 256>>>(ei, E);
    }
    k_final<<<(N + 7) / 8, 256>>>(Wl, bl, bc, out, N);
}

// round 7
// speedup vs baseline: 1.6422x; 1.1726x over previous
#include <cuda_runtime.h>
#include <cuda_bf16.h>

// Problem constants (from reference: N=100000, F=128, Fo=64, E=1600000)
#define NMAX 100000
#define FDIM 128
#define FO   64

__device__ __align__(16) float g_deg[NMAX];
__device__ __align__(16) float g_hs [NMAX * FO];   // h[i] * dinv[i]
__device__ __align__(16) float g_tmp[NMAX * FO];   // aggregate (init = hs -> self loop)

// ---- packed f32x2 helpers (sm_103a) ---------------------------------------
__device__ __forceinline__ unsigned long long pk2(float s) {
    unsigned long long r;
    asm("mov.b64 %0, {%1, %1};" : "=l"(r) : "f"(s));
    return r;
}
__device__ __forceinline__ void fma2(unsigned long long& d,
                                     unsigned long long a,
                                     unsigned long long b) {
    asm("fma.rn.f32x2 %0, %1, %2, %0;" : "+l"(d) : "l"(a), "l"(b));
}
__device__ __forceinline__ float2 unpk2(unsigned long long v) {
    float2 f;
    asm("mov.b64 {%0, %1}, %2;" : "=f"(f.x), "=f"(f.y) : "l"(v));
    return f;
}

// ---------------------------------------------------------------------------
__global__ void k_deg_init(int N) {
    int i = blockIdx.x * blockDim.x + threadIdx.x;
    if (i < N) g_deg[i] = 1.0f;
}

__global__ void k_deg_acc(const int* __restrict__ ei, int E) {
    int t = blockIdx.x * blockDim.x + threadIdx.x;
    int e0 = t * 4;
    if (e0 + 3 < E) {
        int4 d = *(const int4*)(ei + E + e0);
        atomicAdd(&g_deg[d.x], 1.0f);
        atomicAdd(&g_deg[d.y], 1.0f);
        atomicAdd(&g_deg[d.z], 1.0f);
        atomicAdd(&g_deg[d.w], 1.0f);
    } else {
        for (int e = e0; e < E; e++) atomicAdd(&g_deg[ei[E + e]], 1.0f);
    }
}

// ---------------------------------------------------------------------------
// K2: hs = (x @ W^T) * dinv ; tmp = hs (self-loop init)
// 128 threads, 128 rows/block. Thread = 8 rows x 8 cols (32 f32x2 accs).
// Dynamic smem 96KB: W k-major 128x64 (32KB) + x k-major swizzled (64KB).
// Per warp-k: 4 LDS.128 feed 32 fma2 (4x better fma:smem ratio than before).
#define GROWS 128

// x swizzle: 16B-granular rotation. XSW(k,r) keeps each thread's 4 consecutive
// rows contiguous (LDS.128-able) while rotating 16B groups across k.
#define XGRP(k, g)  ((((g) + (k)) & 31) * 4)

__global__ __launch_bounds__(128) void k_gemm(const float* __restrict__ x,
                                              const float* __restrict__ W,
                                              int N) {
    extern __shared__ float smem[];
    float* W_sh = smem;                 // [k*64 + c] = W[c*128 + k]   (32KB)
    float* x_sh = smem + FDIM * FO;     // [k*128 + swizzle(r)]        (64KB)

    int tid = threadIdx.x;
    int row0 = blockIdx.x * GROWS;

    // load W transposed (k-major)
    #pragma unroll
    for (int i = tid; i < FO * FDIM; i += 128) {
        int c = i >> 7;
        int k = i & 127;
        W_sh[k * FO + c] = W[i];
    }

    // load x rows: coalesced global read, swizzled k-major smem store
    #pragma unroll
    for (int i = tid; i < GROWS * FDIM; i += 128) {
        int r = i >> 7;        // 0..127
        int k = i & 127;
        int gr = row0 + r;
        float v = (gr < N) ? x[(long)gr * FDIM + k] : 0.0f;
        x_sh[k * GROWS + XGRP(k, r >> 2) + (r & 3)] = v;
    }
    __syncthreads();

    int rg = tid >> 3;          // 0..15 -> rows rg*8 .. rg*8+7
    int c0 = (tid & 7) << 3;    // 0,8,...,56

    unsigned long long acc[8][4];
    #pragma unroll
    for (int i = 0; i < 8; i++)
        #pragma unroll
        for (int j = 0; j < 4; j++) acc[i][j] = 0ull;

    #pragma unroll 4
    for (int k = 0; k < FDIM; k++) {
        float4 xa = *(const float4*)&x_sh[k * GROWS + XGRP(k, rg * 2)];
        float4 xb = *(const float4*)&x_sh[k * GROWS + XGRP(k, rg * 2 + 1)];
        ulonglong2 w01 = *(const ulonglong2*)&W_sh[k * FO + c0];
        ulonglong2 w23 = *(const ulonglong2*)&W_sh[k * FO + c0 + 4];
        float xs[8] = {xa.x, xa.y, xa.z, xa.w, xb.x, xb.y, xb.z, xb.w};
        #pragma unroll
        for (int i = 0; i < 8; i++) {
            unsigned long long p = pk2(xs[i]);
            fma2(acc[i][0], p, w01.x);
            fma2(acc[i][1], p, w01.y);
            fma2(acc[i][2], p, w23.x);
            fma2(acc[i][3], p, w23.y);
        }
    }

    #pragma unroll
    for (int i = 0; i < 8; i++) {
        int gr = row0 + rg * 8 + i;
        if (gr >= N) continue;
        float dinv = rsqrtf(g_deg[gr]);
        float2 p0 = unpk2(acc[i][0]), p1 = unpk2(acc[i][1]);
        float2 p2 = unpk2(acc[i][2]), p3 = unpk2(acc[i][3]);
        float4 v0 = make_float4(p0.x * dinv, p0.y * dinv, p1.x * dinv, p1.y * dinv);
        float4 v1 = make_float4(p2.x * dinv, p2.y * dinv, p3.x * dinv, p3.y * dinv);
        long base = (long)gr * FO + c0;
        *(float4*)&g_hs [base]     = v0;
        *(float4*)&g_hs [base + 4] = v1;
        *(float4*)&g_tmp[base]     = v0;
        *(float4*)&g_tmp[base + 4] = v1;
    }
}

// ---------------------------------------------------------------------------
// K3: scatter-add: tmp[dst] += hs[src]  — warp per edge, float2 lanes.
// 1 LDG.64 + 1 RED.v2 per edge (2 wf each): same 4 wf/edge floor, fewer instrs.
__global__ __launch_bounds__(256) void k_scatter(const int* __restrict__ ei, int E) {
    int warp = (int)((blockIdx.x * blockDim.x + threadIdx.x) >> 5);
    int lane = threadIdx.x & 31;
    int e0 = warp << 5;
    if (e0 >= E) return;
    int n = E - e0; if (n > 32) n = 32;

    int mysrc = 0, mydst = 0;
    if (lane < n) {
        mysrc = __ldg(ei + e0 + lane);
        mydst = __ldg(ei + E + e0 + lane);
    }

    int j = lane << 1;   // 0,2,...,62
    #pragma unroll 4
    for (int i = 0; i < n; i++) {
        int src = __shfl_sync(0xFFFFFFFFu, mysrc, i);
        int dst = __shfl_sync(0xFFFFFFFFu, mydst, i);
        float2 v = __ldg((const float2*)(g_hs + (long)src * FO + j));
        float* p = g_tmp + (long)dst * FO + j;
        asm volatile("red.global.add.v2.f32 [%0], {%1, %2};"
                     :: "l"(p), "f"(v.x), "f"(v.y) : "memory");
    }
}

// ---------------------------------------------------------------------------
// K4: out = sigmoid( relu(dinv*tmp + b_conv) . W_lin + b_lin )  — warp per node
__global__ void k_final(const float* __restrict__ Wl,
                        const float* __restrict__ bl,
                        const float* __restrict__ bconv,
                        float* __restrict__ out, int N) {
    int warp = (int)((blockIdx.x * blockDim.x + threadIdx.x) >> 5);
    int lane = threadIdx.x & 31;
    if (warp >= N) return;

    float dinv = rsqrtf(g_deg[warp]);
    float2 tv = *(const float2*)&g_tmp[(long)warp * FO + lane * 2];
    float2 wv = *(const float2*)&Wl[lane * 2];
    float2 bc = *(const float2*)&bconv[lane * 2];

    float v0 = fmaxf(fmaf(tv.x, dinv, bc.x), 0.0f);
    float v1 = fmaxf(fmaf(tv.y, dinv, bc.y), 0.0f);
    float s  = v0 * wv.x + v1 * wv.y;

    #pragma unroll
    for (int o = 16; o; o >>= 1) s += __shfl_xor_sync(0xFFFFFFFFu, s, o);

    if (lane == 0) {
        float z = s + bl[0];
        out[warp] = 1.0f / (1.0f + expf(-z));
    }
}

// ---------------------------------------------------------------------------
extern "C" void kernel_launch(void* const* d_in, const int* in_sizes, int n_in,
                              void* d_out, int out_size) {
    const float* x     = (const float*)d_in[0];
    const int*   ei    = (const int*)  d_in[1];
    const float* Wc    = (const float*)d_in[2];
    const float* bc    = (const float*)d_in[3];
    const float* Wl    = (const float*)d_in[4];
    const float* bl    = (const float*)d_in[5];
    float*       out   = (float*)d_out;

    int N = in_sizes[0] / FDIM;
    int E = in_sizes[1] / 2;
    if (N > NMAX) N = NMAX;

    const int GEMM_SMEM = (FDIM * FO + GROWS * FDIM) * (int)sizeof(float); // 96KB
    cudaFuncSetAttribute(k_gemm, cudaFuncAttributeMaxDynamicSharedMemorySize,
                         GEMM_SMEM);

    k_deg_init<<<(N + 255) / 256, 256>>>(N);
    k_deg_acc <<<((E + 3) / 4 + 255) / 256, 256>>>(ei, E);
    k_gemm    <<<(N + GROWS - 1) / GROWS, 128, GEMM_SMEM>>>(x, Wc, N);
    {
        int nwarp  = (E + 31) / 32;
        int blocks = (nwarp + 7) / 8;
        k_scatter<<<blocks, 256>>>(ei, E);
    }
    k_final<<<(N + 7) / 8, 256>>>(Wl, bl, bc, out, N);
}